// round 2
// baseline (speedup 1.0000x reference)
#include <cuda_runtime.h>
#include <cuda_bf16.h>

#define SEQ   128
#define BATCH 256
#define OBS   64
#define HID   1024
#define G4    4096          // 4*HID
#define K0L0  64            // x part of layer0 K
#define KTOT0 1088          // 64 + 1024
#define KTOT1 2048          // 1024 + 1024
#define BH    (BATCH*HID)

// ---------------- scratch (static device memory; no allocations) ----------------
__device__ float g_PW0[(size_t)G4 * KTOT0];   // packed layer0 weights, row = unit*4+gate
__device__ float g_PW1[(size_t)G4 * KTOT1];   // packed layer1 weights
__device__ float g_PB0[G4];
__device__ float g_PB1[G4];
__device__ float g_h0s[2][BH];                // layer0 h state ping-pong
__device__ float g_c0s[2][BH];
__device__ float g_c1s[2][BH];
__device__ float g_hs[(size_t)SEQ * BH];      // layer1 h per step (also layer1 state source)
__device__ float g_ln[(size_t)SEQ * BH];      // layernorm output
__device__ float g_a1[(size_t)SEQ * BATCH * 512];
__device__ float g_a2[(size_t)SEQ * BATCH * 128];
__device__ float g_a3[(size_t)SEQ * BATCH * 64];

// ---------------- helpers ----------------
__device__ __forceinline__ unsigned tf32_bits(float x) {
    unsigned u; asm("cvt.rna.tf32.f32 %0, %1;" : "=r"(u) : "f"(x)); return u;
}
__device__ __forceinline__ float tf32f(float x) { return __uint_as_float(tf32_bits(x)); }

__device__ __forceinline__ void mma_tf32(float* c, const unsigned* a, const unsigned* b) {
    asm volatile(
        "mma.sync.aligned.m16n8k8.row.col.f32.tf32.tf32.f32 "
        "{%0,%1,%2,%3}, {%4,%5,%6,%7}, {%8,%9}, {%0,%1,%2,%3};"
        : "+f"(c[0]), "+f"(c[1]), "+f"(c[2]), "+f"(c[3])
        : "r"(a[0]), "r"(a[1]), "r"(a[2]), "r"(a[3]), "r"(b[0]), "r"(b[1]));
}

__device__ __forceinline__ float sigm(float x) { return 1.f / (1.f + __expf(-x)); }
__device__ __forceinline__ float eluf(float x) { return x > 0.f ? x : (__expf(x) - 1.f); }

// ---------------- weight packing (tf32-rounded, gate-interleaved rows) ----------------
__global__ void pack_kernel(const float* __restrict__ Wih0, const float* __restrict__ Whh0,
                            const float* __restrict__ bih0, const float* __restrict__ bhh0,
                            const float* __restrict__ Wih1, const float* __restrict__ Whh1,
                            const float* __restrict__ bih1, const float* __restrict__ bhh1) {
    int j = blockIdx.x;              // packed row: j = unit*4 + gate
    int u = j >> 2, g = j & 3;
    int src = g * HID + u;           // original row in (4H, K) weight
    if (blockIdx.y == 0) {
        for (int k = threadIdx.x; k < KTOT0; k += blockDim.x) {
            float v = (k < K0L0) ? Wih0[src * OBS + k] : Whh0[src * HID + (k - K0L0)];
            g_PW0[(size_t)j * KTOT0 + k] = tf32f(v);
        }
        if (threadIdx.x == 0) g_PB0[j] = bih0[src] + bhh0[src];
    } else {
        for (int k = threadIdx.x; k < KTOT1; k += blockDim.x) {
            float v = (k < HID) ? Wih1[src * HID + k] : Whh1[src * HID + (k - HID)];
            g_PW1[(size_t)j * KTOT1 + k] = tf32f(v);
        }
        if (threadIdx.x == 0) g_PB1[j] = bih1[src] + bhh1[src];
    }
}

// ---------------- fused LSTM step (GEMM over concat-K + cell epilogue) ----------------
// grid (2, 64): blockIdx.x = M tile (128 rows), blockIdx.y = 16-unit tile (64 packed cols)
__global__ __launch_bounds__(256) void lstm_step_kernel(
    const float* __restrict__ x, const int* __restrict__ done,
    const float* __restrict__ in_h0, const float* __restrict__ in_c0,
    int t, int layer)
{
    __shared__ float As[128 * 36];
    __shared__ float Bs[64 * 36];
    __shared__ float mrow[128];

    const float *A0, *Aprev, *cprev, *PW, *PB;
    float *cout_, *hout;
    int K0len, Ktot;
    if (layer == 0) {
        A0 = x + (size_t)t * BATCH * OBS; K0len = K0L0; Ktot = KTOT0;
        PW = g_PW0; PB = g_PB0;
        Aprev = t ? g_h0s[(t - 1) & 1] : in_h0;
        cprev = t ? g_c0s[(t - 1) & 1] : in_c0;
        cout_ = g_c0s[t & 1]; hout = g_h0s[t & 1];
    } else {
        A0 = g_h0s[t & 1]; K0len = HID; Ktot = KTOT1;
        PW = g_PW1; PB = g_PB1;
        Aprev = t ? (g_hs + (size_t)(t - 1) * BH) : (in_h0 + BH);
        cprev = t ? g_c1s[(t - 1) & 1] : (in_c0 + BH);
        cout_ = g_c1s[t & 1]; hout = g_hs + (size_t)t * BH;
    }
    const int* dt = done + t * BATCH;

    int tid = threadIdx.x, lane = tid & 31, warp = tid >> 5;
    int m0 = blockIdx.x * 128;
    int nrow0 = blockIdx.y * 64;
    int wm = warp >> 1, wn = warp & 1;     // 4x2 warp grid, 32x32 per warp
    int ar = lane >> 2, ac = lane & 3;

    for (int r = tid; r < 128; r += 256) mrow[r] = 1.f - (float)dt[m0 + r];

    float acc[2][4][4];
#pragma unroll
    for (int i = 0; i < 2; i++)
#pragma unroll
        for (int j = 0; j < 4; j++)
#pragma unroll
            for (int k = 0; k < 4; k++) acc[i][j][k] = 0.f;

    for (int kk = 0; kk < Ktot; kk += 32) {
        __syncthreads();
        // A tile: 128 x 32 (concat x/h with mask on the recurrent part)
        for (int e = tid; e < 128 * 8; e += 256) {
            int r = e >> 3, kv = e & 7;
            int k = kk + kv * 4;
            float4 v;
            if (k < K0len) {
                v = *(const float4*)(A0 + (size_t)(m0 + r) * K0len + k);
            } else {
                v = *(const float4*)(Aprev + (size_t)(m0 + r) * HID + (k - K0len));
                float mm = mrow[r];
                v.x *= mm; v.y *= mm; v.z *= mm; v.w *= mm;
            }
            float* d = &As[r * 36 + kv * 4];
            d[0] = tf32f(v.x); d[1] = tf32f(v.y); d[2] = tf32f(v.z); d[3] = tf32f(v.w);
        }
        // B tile: 64 x 32 (already tf32-rounded in pack)
        for (int e = tid; e < 64 * 8; e += 256) {
            int r = e >> 3, kv = e & 7;
            float4 v = *(const float4*)(PW + (size_t)(nrow0 + r) * Ktot + kk + kv * 4);
            float* d = &Bs[r * 36 + kv * 4];
            d[0] = v.x; d[1] = v.y; d[2] = v.z; d[3] = v.w;
        }
        __syncthreads();
#pragma unroll
        for (int ks = 0; ks < 32; ks += 8) {
            unsigned a[2][4], b[4][2];
#pragma unroll
            for (int mf = 0; mf < 2; mf++) {
                int rb = wm * 32 + mf * 16 + ar;
                a[mf][0] = __float_as_uint(As[rb * 36 + ks + ac]);
                a[mf][1] = __float_as_uint(As[(rb + 8) * 36 + ks + ac]);
                a[mf][2] = __float_as_uint(As[rb * 36 + ks + ac + 4]);
                a[mf][3] = __float_as_uint(As[(rb + 8) * 36 + ks + ac + 4]);
            }
#pragma unroll
            for (int nf = 0; nf < 4; nf++) {
                int nb = wn * 32 + nf * 8 + ar;
                b[nf][0] = __float_as_uint(Bs[nb * 36 + ks + ac]);
                b[nf][1] = __float_as_uint(Bs[nb * 36 + ks + ac + 4]);
            }
#pragma unroll
            for (int mf = 0; mf < 2; mf++)
#pragma unroll
                for (int nf = 0; nf < 4; nf++)
                    mma_tf32(acc[mf][nf], a[mf], b[nf]);
        }
    }

    // epilogue: bias + gate merge (shfl with lane^1) + LSTM cell
#pragma unroll
    for (int mf = 0; mf < 2; mf++) {
#pragma unroll
        for (int nf = 0; nf < 4; nf++) {
            int npl = wn * 32 + nf * 8 + ac * 2;
            int nglob = nrow0 + npl;               // packed col = unit*4 + gate
            float bb0 = PB[nglob], bb1 = PB[nglob + 1];
            float v0 = acc[mf][nf][0] + bb0;
            float v1 = acc[mf][nf][1] + bb1;
            float v2 = acc[mf][nf][2] + bb0;
            float v3 = acc[mf][nf][3] + bb1;
            float p0 = __shfl_xor_sync(0xffffffffu, v0, 1);
            float p1 = __shfl_xor_sync(0xffffffffu, v1, 1);
            float p2 = __shfl_xor_sync(0xffffffffu, v2, 1);
            float p3 = __shfl_xor_sync(0xffffffffu, v3, 1);
            if ((lane & 1) == 0) {                 // even lanes hold (i,f); partner holds (g,o)
                int u = nglob >> 2;
                int r0 = m0 + wm * 32 + mf * 16 + ar;
                // row r0
                {
                    float mm = mrow[r0 - m0];
                    float cp = cprev[(size_t)r0 * HID + u] * mm;
                    float cn = sigm(v1) * cp + sigm(v0) * tanhf(p0);
                    float hn = sigm(p1) * tanhf(cn);
                    cout_[(size_t)r0 * HID + u] = cn;
                    hout[(size_t)r0 * HID + u] = hn;
                }
                // row r0+8
                {
                    int r1 = r0 + 8;
                    float mm = mrow[r1 - m0];
                    float cp = cprev[(size_t)r1 * HID + u] * mm;
                    float cn = sigm(v3) * cp + sigm(v2) * tanhf(p2);
                    float hn = sigm(p3) * tanhf(cn);
                    cout_[(size_t)r1 * HID + u] = cn;
                    hout[(size_t)r1 * HID + u] = hn;
                }
            }
        }
    }
}

// ---------------- LayerNorm over hidden (32768 rows x 1024) ----------------
__global__ __launch_bounds__(256) void ln_kernel(const float* __restrict__ gam,
                                                 const float* __restrict__ bet) {
    int row = blockIdx.x;
    int tid = threadIdx.x, lane = tid & 31, w = tid >> 5;
    const float4 v = ((const float4*)(g_hs + (size_t)row * HID))[tid];
    float s = v.x + v.y + v.z + v.w;
    float q = v.x * v.x + v.y * v.y + v.z * v.z + v.w * v.w;
    __shared__ float sh[18];
#pragma unroll
    for (int o = 16; o; o >>= 1) {
        s += __shfl_xor_sync(0xffffffffu, s, o);
        q += __shfl_xor_sync(0xffffffffu, q, o);
    }
    if (!lane) { sh[w] = s; sh[w + 8] = q; }
    __syncthreads();
    if (tid == 0) {
        float S = 0.f, Q = 0.f;
        for (int i = 0; i < 8; i++) { S += sh[i]; Q += sh[i + 8]; }
        float mu = S * (1.f / HID);
        float var = Q * (1.f / HID) - mu * mu;
        sh[16] = mu; sh[17] = rsqrtf(var + 1e-5f);
    }
    __syncthreads();
    float mu = sh[16], rs = sh[17];
    float4 g4 = ((const float4*)gam)[tid];
    float4 b4 = ((const float4*)bet)[tid];
    float4 o;
    o.x = (v.x - mu) * rs * g4.x + b4.x;
    o.y = (v.y - mu) * rs * g4.y + b4.y;
    o.z = (v.z - mu) * rs * g4.z + b4.z;
    o.w = (v.w - mu) * rs * g4.w + b4.w;
    ((float4*)(g_ln + (size_t)row * HID))[tid] = o;
}

// ---------------- MLP GEMM + ELU: C[M,N] = elu(A[M,K] @ W[N,K]^T + b) ----------------
// grid (256, N/64); which: 0 -> ln->a1 (N=512,K=1024), 1 -> a1->a2 (128,512), 2 -> a2->a3 (64,128)
__global__ __launch_bounds__(256) void mlp_gemm(const float* __restrict__ W,
                                                const float* __restrict__ bias, int which) {
    __shared__ float As[128 * 36];
    __shared__ float Bs[64 * 36];
    const float* A; float* C; int N, K;
    if (which == 0)      { A = g_ln; C = g_a1; N = 512; K = 1024; }
    else if (which == 1) { A = g_a1; C = g_a2; N = 128; K = 512; }
    else                 { A = g_a2; C = g_a3; N = 64;  K = 128; }

    int tid = threadIdx.x, lane = tid & 31, warp = tid >> 5;
    int m0 = blockIdx.x * 128;
    int n0 = blockIdx.y * 64;
    int wm = warp >> 1, wn = warp & 1;
    int ar = lane >> 2, ac = lane & 3;

    float acc[2][4][4];
#pragma unroll
    for (int i = 0; i < 2; i++)
#pragma unroll
        for (int j = 0; j < 4; j++)
#pragma unroll
            for (int k = 0; k < 4; k++) acc[i][j][k] = 0.f;

    for (int kk = 0; kk < K; kk += 32) {
        __syncthreads();
        for (int e = tid; e < 128 * 8; e += 256) {
            int r = e >> 3, kv = e & 7;
            float4 v = *(const float4*)(A + (size_t)(m0 + r) * K + kk + kv * 4);
            float* d = &As[r * 36 + kv * 4];
            d[0] = tf32f(v.x); d[1] = tf32f(v.y); d[2] = tf32f(v.z); d[3] = tf32f(v.w);
        }
        for (int e = tid; e < 64 * 8; e += 256) {
            int r = e >> 3, kv = e & 7;
            float4 v = *(const float4*)(W + (size_t)(n0 + r) * K + kk + kv * 4);
            float* d = &Bs[r * 36 + kv * 4];
            d[0] = tf32f(v.x); d[1] = tf32f(v.y); d[2] = tf32f(v.z); d[3] = tf32f(v.w);
        }
        __syncthreads();
#pragma unroll
        for (int ks = 0; ks < 32; ks += 8) {
            unsigned a[2][4], b[4][2];
#pragma unroll
            for (int mf = 0; mf < 2; mf++) {
                int rb = wm * 32 + mf * 16 + ar;
                a[mf][0] = __float_as_uint(As[rb * 36 + ks + ac]);
                a[mf][1] = __float_as_uint(As[(rb + 8) * 36 + ks + ac]);
                a[mf][2] = __float_as_uint(As[rb * 36 + ks + ac + 4]);
                a[mf][3] = __float_as_uint(As[(rb + 8) * 36 + ks + ac + 4]);
            }
#pragma unroll
            for (int nf = 0; nf < 4; nf++) {
                int nb = wn * 32 + nf * 8 + ar;
                b[nf][0] = __float_as_uint(Bs[nb * 36 + ks + ac]);
                b[nf][1] = __float_as_uint(Bs[nb * 36 + ks + ac + 4]);
            }
#pragma unroll
            for (int mf = 0; mf < 2; mf++)
#pragma unroll
                for (int nf = 0; nf < 4; nf++)
                    mma_tf32(acc[mf][nf], a[mf], b[nf]);
        }
    }

#pragma unroll
    for (int mf = 0; mf < 2; mf++) {
#pragma unroll
        for (int nf = 0; nf < 4; nf++) {
            int col = n0 + wn * 32 + nf * 8 + ac * 2;
            int r0 = m0 + wm * 32 + mf * 16 + ar;
            float b0 = bias[col], b1 = bias[col + 1];
            C[(size_t)r0 * N + col]       = eluf(acc[mf][nf][0] + b0);
            C[(size_t)r0 * N + col + 1]   = eluf(acc[mf][nf][1] + b1);
            C[(size_t)(r0 + 8) * N + col]     = eluf(acc[mf][nf][2] + b0);
            C[(size_t)(r0 + 8) * N + col + 1] = eluf(acc[mf][nf][3] + b1);
        }
    }
}

// ---------------- final value head: out[r] = dot(a3[r,:64], Wv) + bv ----------------
__global__ __launch_bounds__(256) void value_kernel(const float* __restrict__ Wv,
                                                    const float* __restrict__ bv,
                                                    float* __restrict__ out) {
    int warp = threadIdx.x >> 5, lane = threadIdx.x & 31;
    int row = blockIdx.x * 8 + warp;
    const float* a = g_a3 + (size_t)row * 64;
    float s = a[lane] * Wv[lane] + a[lane + 32] * Wv[lane + 32];
#pragma unroll
    for (int o = 16; o; o >>= 1) s += __shfl_xor_sync(0xffffffffu, s, o);
    if (lane == 0) out[row] = s + bv[0];
}

// ---------------- copy final states into output ----------------
__global__ void copy_states(float* __restrict__ out) {
    const int last = (SEQ - 1) & 1;                 // ping-pong slot of final step
    for (size_t i = blockIdx.x * blockDim.x + threadIdx.x; i < 4 * (size_t)BH;
         i += (size_t)gridDim.x * blockDim.x) {
        float v;
        if (i < BH)            v = g_h0s[last][i];
        else if (i < 2 * (size_t)BH) v = g_hs[(size_t)(SEQ - 1) * BH + (i - BH)];
        else if (i < 3 * (size_t)BH) v = g_c0s[last][i - 2 * BH];
        else                   v = g_c1s[last][i - 3 * BH];
        out[SEQ * BATCH + i] = v;
    }
}

// ---------------- launch ----------------
extern "C" void kernel_launch(void* const* d_in, const int* in_sizes, int n_in,
                              void* d_out, int out_size) {
    const float* x     = (const float*)d_in[0];
    const int*   done  = (const int*)  d_in[1];
    const float* h0    = (const float*)d_in[2];
    const float* c0    = (const float*)d_in[3];
    const float* Wih0  = (const float*)d_in[4];
    const float* Whh0  = (const float*)d_in[5];
    const float* bih0  = (const float*)d_in[6];
    const float* bhh0  = (const float*)d_in[7];
    const float* Wih1  = (const float*)d_in[8];
    const float* Whh1  = (const float*)d_in[9];
    const float* bih1  = (const float*)d_in[10];
    const float* bhh1  = (const float*)d_in[11];
    const float* ln_g  = (const float*)d_in[12];
    const float* ln_b  = (const float*)d_in[13];
    const float* W1    = (const float*)d_in[14];
    const float* b1    = (const float*)d_in[15];
    const float* W2    = (const float*)d_in[16];
    const float* b2    = (const float*)d_in[17];
    const float* W3    = (const float*)d_in[18];
    const float* b3    = (const float*)d_in[19];
    const float* Wv    = (const float*)d_in[20];
    const float* bv    = (const float*)d_in[21];
    float* out = (float*)d_out;

    pack_kernel<<<dim3(G4, 2), 256>>>(Wih0, Whh0, bih0, bhh0, Wih1, Whh1, bih1, bhh1);

    for (int t = 0; t < SEQ; t++) {
        lstm_step_kernel<<<dim3(2, 64), 256>>>(x, done, h0, c0, t, 0);
        lstm_step_kernel<<<dim3(2, 64), 256>>>(x, done, h0, c0, t, 1);
    }

    ln_kernel<<<SEQ * BATCH, 256>>>(ln_g, ln_b);
    mlp_gemm<<<dim3(256, 8), 256>>>(W1, b1, 0);
    mlp_gemm<<<dim3(256, 2), 256>>>(W2, b2, 1);
    mlp_gemm<<<dim3(256, 1), 256>>>(W3, b3, 2);
    value_kernel<<<SEQ * BATCH / 8, 256>>>(Wv, bv, out);
    copy_states<<<2048, 256>>>(out);
}

// round 4
// speedup vs baseline: 2.1642x; 2.1642x over previous
#include <cuda_runtime.h>
#include <cuda_bf16.h>

#define SEQ   128
#define BATCH 256
#define OBS   64
#define HID   1024
#define G4    4096          // 4*HID
#define K0L0  64            // x part of layer0 K
#define KTOT0 1088          // 64 + 1024
#define KTOT1 2048          // 1024 + 1024
#define BH    (BATCH*HID)

// smem layout (floats): As 2*128*36, Bs 2*64*36, mrow 128
#define AS_STRIDE 36
#define AS_BUF    (128*AS_STRIDE)     // 4608
#define BS_BUF    (64*AS_STRIDE)      // 2304
#define SMEM_FLOATS (2*AS_BUF + 2*BS_BUF + 128)
#define SMEM_BYTES  (SMEM_FLOATS*4)

// ---------------- scratch (static device memory; no allocations) ----------------
__device__ float g_PW0[(size_t)G4 * KTOT0];   // packed layer0 weights, row = unit*4+gate
__device__ float g_PW1[(size_t)G4 * KTOT1];   // packed layer1 weights
__device__ float g_PB0[G4];
__device__ float g_PB1[G4];
__device__ float g_h0s[2][BH];                // layer0 h state ping-pong
__device__ float g_c0s[2][BH];
__device__ float g_c1s[2][BH];
__device__ float g_hs[(size_t)SEQ * BH];      // layer1 h per step
__device__ float g_ln[(size_t)SEQ * BH];      // layernorm output
__device__ float g_a1[(size_t)SEQ * BATCH * 512];
__device__ float g_a2[(size_t)SEQ * BATCH * 128];
__device__ float g_a3[(size_t)SEQ * BATCH * 64];

// ---------------- helpers ----------------
__device__ __forceinline__ unsigned tf32_bits(float x) {
    unsigned u; asm("cvt.rna.tf32.f32 %0, %1;" : "=r"(u) : "f"(x)); return u;
}
__device__ __forceinline__ float tf32f(float x) { return __uint_as_float(tf32_bits(x)); }

__device__ __forceinline__ void mma_tf32(float* c, const unsigned* a, const unsigned* b) {
    asm volatile(
        "mma.sync.aligned.m16n8k8.row.col.f32.tf32.tf32.f32 "
        "{%0,%1,%2,%3}, {%4,%5,%6,%7}, {%8,%9}, {%0,%1,%2,%3};"
        : "+f"(c[0]), "+f"(c[1]), "+f"(c[2]), "+f"(c[3])
        : "r"(a[0]), "r"(a[1]), "r"(a[2]), "r"(a[3]), "r"(b[0]), "r"(b[1]));
}

__device__ __forceinline__ float sigm(float x) { return 1.f / (1.f + __expf(-x)); }
__device__ __forceinline__ float eluf(float x) { return x > 0.f ? x : (__expf(x) - 1.f); }

// ---------------- weight packing (tf32-rounded, gate-interleaved rows) ----------------
__global__ void pack_kernel(const float* __restrict__ Wih0, const float* __restrict__ Whh0,
                            const float* __restrict__ bih0, const float* __restrict__ bhh0,
                            const float* __restrict__ Wih1, const float* __restrict__ Whh1,
                            const float* __restrict__ bih1, const float* __restrict__ bhh1) {
    int j = blockIdx.x;              // packed row: j = unit*4 + gate
    int u = j >> 2, g = j & 3;
    int src = g * HID + u;           // original row in (4H, K) weight
    if (blockIdx.y == 0) {
        for (int k = threadIdx.x; k < KTOT0; k += blockDim.x) {
            float v = (k < K0L0) ? Wih0[src * OBS + k] : Whh0[src * HID + (k - K0L0)];
            g_PW0[(size_t)j * KTOT0 + k] = tf32f(v);
        }
        if (threadIdx.x == 0) g_PB0[j] = bih0[src] + bhh0[src];
    } else {
        for (int k = threadIdx.x; k < KTOT1; k += blockDim.x) {
            float v = (k < HID) ? Wih1[src * HID + k] : Whh1[src * HID + (k - HID)];
            g_PW1[(size_t)j * KTOT1 + k] = tf32f(v);
        }
        if (threadIdx.x == 0) g_PB1[j] = bih1[src] + bhh1[src];
    }
}

// ---------------- fused LSTM step, double-buffered pipelined GEMM + cell ----------------
// grid (2, 64): blockIdx.x = M tile (128 rows), blockIdx.y = 16-unit tile (64 packed cols)
__global__ __launch_bounds__(256) void lstm_step_kernel(
    const float* __restrict__ x, const int* __restrict__ done,
    const float* __restrict__ in_h0, const float* __restrict__ in_c0,
    int t, int layer)
{
    extern __shared__ float sdyn[];
    float* As   = sdyn;                      // 2 buffers of 128x32 (stride 36)
    float* Bs   = sdyn + 2 * AS_BUF;         // 2 buffers of 64x32  (stride 36)
    float* mrow = sdyn + 2 * AS_BUF + 2 * BS_BUF;

    const float *A0, *Aprev, *cprev, *PW, *PB;
    float *cout_, *hout;
    int K0len, Ktot;
    if (layer == 0) {
        A0 = x + (size_t)t * BATCH * OBS; K0len = K0L0; Ktot = KTOT0;
        PW = g_PW0; PB = g_PB0;
        Aprev = t ? g_h0s[(t - 1) & 1] : in_h0;
        cprev = t ? g_c0s[(t - 1) & 1] : in_c0;
        cout_ = g_c0s[t & 1]; hout = g_h0s[t & 1];
    } else {
        A0 = g_h0s[t & 1]; K0len = HID; Ktot = KTOT1;
        PW = g_PW1; PB = g_PB1;
        Aprev = t ? (g_hs + (size_t)(t - 1) * BH) : (in_h0 + BH);
        cprev = t ? g_c1s[(t - 1) & 1] : (in_c0 + BH);
        cout_ = g_c1s[t & 1]; hout = g_hs + (size_t)t * BH;
    }
    const int* dt = done + t * BATCH;

    int tid = threadIdx.x, lane = tid & 31, warp = tid >> 5;
    int m0 = blockIdx.x * 128;
    int nrow0 = blockIdx.y * 64;
    int wm = warp >> 1, wn = warp & 1;     // 4x2 warp grid, 32x32 per warp
    int ar = lane >> 2, ac = lane & 3;

    for (int r = tid; r < 128; r += 256) mrow[r] = 1.f - (float)dt[m0 + r];
    __syncthreads();                        // mrow visible before any A store

    float acc[2][4][4];
#pragma unroll
    for (int i = 0; i < 2; i++)
#pragma unroll
        for (int j = 0; j < 4; j++)
#pragma unroll
            for (int k = 0; k < 4; k++) acc[i][j][k] = 0.f;

    const int NIT = Ktot / 32;
    float4 rA[4], rB[2];

    // ---- prologue: load + store chunk 0 into buffer 0 ----
#pragma unroll
    for (int i = 0; i < 4; i++) {
        int q = tid + i * 256;              // q in [0,1024): r=q>>3, kv=q&7
        int r = q >> 3, k = (q & 7) * 4;
        if (k < K0len) rA[i] = *(const float4*)(A0 + (size_t)(m0 + r) * K0len + k);
        else           rA[i] = *(const float4*)(Aprev + (size_t)(m0 + r) * HID + (k - K0len));
    }
#pragma unroll
    for (int i = 0; i < 2; i++) {
        int q = tid + i * 256;              // q in [0,512)
        int r = q >> 3, k = (q & 7) * 4;
        rB[i] = *(const float4*)(PW + (size_t)(nrow0 + r) * Ktot + k);
    }
#pragma unroll
    for (int i = 0; i < 4; i++) {
        int q = tid + i * 256;
        int r = q >> 3, kv = q & 7, k = kv * 4;
        float4 v = rA[i];
        if (k >= K0len) { float mm = mrow[r]; v.x *= mm; v.y *= mm; v.z *= mm; v.w *= mm; }
        float* d = &As[r * AS_STRIDE + kv * 4];
        d[0] = tf32f(v.x); d[1] = tf32f(v.y); d[2] = tf32f(v.z); d[3] = tf32f(v.w);
    }
#pragma unroll
    for (int i = 0; i < 2; i++) {
        int q = tid + i * 256;
        int r = q >> 3, kv = q & 7;
        float* d = &Bs[r * AS_STRIDE + kv * 4];
        d[0] = rB[i].x; d[1] = rB[i].y; d[2] = rB[i].z; d[3] = rB[i].w;
    }
    __syncthreads();

    // ---- mainloop: prefetch next chunk to regs, compute current, store to alt buffer ----
    for (int it = 0; it < NIT; it++) {
        int buf = it & 1;
        bool more = (it + 1 < NIT);
        int kkn = (it + 1) * 32;

        if (more) {
#pragma unroll
            for (int i = 0; i < 4; i++) {
                int q = tid + i * 256;
                int r = q >> 3, k = kkn + (q & 7) * 4;
                if (k < K0len) rA[i] = *(const float4*)(A0 + (size_t)(m0 + r) * K0len + k);
                else           rA[i] = *(const float4*)(Aprev + (size_t)(m0 + r) * HID + (k - K0len));
            }
#pragma unroll
            for (int i = 0; i < 2; i++) {
                int q = tid + i * 256;
                int r = q >> 3, k = kkn + (q & 7) * 4;
                rB[i] = *(const float4*)(PW + (size_t)(nrow0 + r) * Ktot + k);
            }
        }

        const float* Ab = As + buf * AS_BUF;
        const float* Bb = Bs + buf * BS_BUF;
#pragma unroll
        for (int ks = 0; ks < 32; ks += 8) {
            unsigned a[2][4], b[4][2];
#pragma unroll
            for (int mf = 0; mf < 2; mf++) {
                int rb = wm * 32 + mf * 16 + ar;
                a[mf][0] = __float_as_uint(Ab[rb * AS_STRIDE + ks + ac]);
                a[mf][1] = __float_as_uint(Ab[(rb + 8) * AS_STRIDE + ks + ac]);
                a[mf][2] = __float_as_uint(Ab[rb * AS_STRIDE + ks + ac + 4]);
                a[mf][3] = __float_as_uint(Ab[(rb + 8) * AS_STRIDE + ks + ac + 4]);
            }
#pragma unroll
            for (int nf = 0; nf < 4; nf++) {
                int nb = wn * 32 + nf * 8 + ar;
                b[nf][0] = __float_as_uint(Bb[nb * AS_STRIDE + ks + ac]);
                b[nf][1] = __float_as_uint(Bb[nb * AS_STRIDE + ks + ac + 4]);
            }
#pragma unroll
            for (int mf = 0; mf < 2; mf++)
#pragma unroll
                for (int nf = 0; nf < 4; nf++)
                    mma_tf32(acc[mf][nf], a[mf], b[nf]);
        }

        if (more) {
            float* Aw = As + (buf ^ 1) * AS_BUF;
            float* Bw = Bs + (buf ^ 1) * BS_BUF;
#pragma unroll
            for (int i = 0; i < 4; i++) {
                int q = tid + i * 256;
                int r = q >> 3, kv = q & 7, k = kkn + kv * 4;
                float4 v = rA[i];
                if (k >= K0len) { float mm = mrow[r]; v.x *= mm; v.y *= mm; v.z *= mm; v.w *= mm; }
                float* d = &Aw[r * AS_STRIDE + kv * 4];
                d[0] = tf32f(v.x); d[1] = tf32f(v.y); d[2] = tf32f(v.z); d[3] = tf32f(v.w);
            }
#pragma unroll
            for (int i = 0; i < 2; i++) {
                int q = tid + i * 256;
                int r = q >> 3, kv = q & 7;
                float* d = &Bw[r * AS_STRIDE + kv * 4];
                d[0] = rB[i].x; d[1] = rB[i].y; d[2] = rB[i].z; d[3] = rB[i].w;
            }
        }
        __syncthreads();
    }

    // ---- epilogue: bias + gate merge (shfl lane^1) + LSTM cell ----
#pragma unroll
    for (int mf = 0; mf < 2; mf++) {
#pragma unroll
        for (int nf = 0; nf < 4; nf++) {
            int npl = wn * 32 + nf * 8 + ac * 2;
            int nglob = nrow0 + npl;               // packed col = unit*4 + gate
            float bb0 = PB[nglob], bb1 = PB[nglob + 1];
            float v0 = acc[mf][nf][0] + bb0;
            float v1 = acc[mf][nf][1] + bb1;
            float v2 = acc[mf][nf][2] + bb0;
            float v3 = acc[mf][nf][3] + bb1;
            float p0 = __shfl_xor_sync(0xffffffffu, v0, 1);
            float p1 = __shfl_xor_sync(0xffffffffu, v1, 1);
            float p2 = __shfl_xor_sync(0xffffffffu, v2, 1);
            float p3 = __shfl_xor_sync(0xffffffffu, v3, 1);
            if ((lane & 1) == 0) {                 // even lanes hold (i,f); partner holds (g,o)
                int u = nglob >> 2;
                int r0 = m0 + wm * 32 + mf * 16 + ar;
                {
                    float mm = mrow[r0 - m0];
                    float cp = cprev[(size_t)r0 * HID + u] * mm;
                    float cn = sigm(v1) * cp + sigm(v0) * tanhf(p0);
                    float hn = sigm(p1) * tanhf(cn);
                    cout_[(size_t)r0 * HID + u] = cn;
                    hout[(size_t)r0 * HID + u] = hn;
                }
                {
                    int r1 = r0 + 8;
                    float mm = mrow[r1 - m0];
                    float cp = cprev[(size_t)r1 * HID + u] * mm;
                    float cn = sigm(v3) * cp + sigm(v2) * tanhf(p2);
                    float hn = sigm(p3) * tanhf(cn);
                    cout_[(size_t)r1 * HID + u] = cn;
                    hout[(size_t)r1 * HID + u] = hn;
                }
            }
        }
    }
}

// ---------------- LayerNorm over hidden (32768 rows x 1024) ----------------
__global__ __launch_bounds__(256) void ln_kernel(const float* __restrict__ gam,
                                                 const float* __restrict__ bet) {
    int row = blockIdx.x;
    int tid = threadIdx.x, lane = tid & 31, w = tid >> 5;
    const float4 v = ((const float4*)(g_hs + (size_t)row * HID))[tid];
    float s = v.x + v.y + v.z + v.w;
    float q = v.x * v.x + v.y * v.y + v.z * v.z + v.w * v.w;
    __shared__ float sh[18];
#pragma unroll
    for (int o = 16; o; o >>= 1) {
        s += __shfl_xor_sync(0xffffffffu, s, o);
        q += __shfl_xor_sync(0xffffffffu, q, o);
    }
    if (!lane) { sh[w] = s; sh[w + 8] = q; }
    __syncthreads();
    if (tid == 0) {
        float S = 0.f, Q = 0.f;
        for (int i = 0; i < 8; i++) { S += sh[i]; Q += sh[i + 8]; }
        float mu = S * (1.f / HID);
        float var = Q * (1.f / HID) - mu * mu;
        sh[16] = mu; sh[17] = rsqrtf(var + 1e-5f);
    }
    __syncthreads();
    float mu = sh[16], rs = sh[17];
    float4 g4 = ((const float4*)gam)[tid];
    float4 b4 = ((const float4*)bet)[tid];
    float4 o;
    o.x = (v.x - mu) * rs * g4.x + b4.x;
    o.y = (v.y - mu) * rs * g4.y + b4.y;
    o.z = (v.z - mu) * rs * g4.z + b4.z;
    o.w = (v.w - mu) * rs * g4.w + b4.w;
    ((float4*)(g_ln + (size_t)row * HID))[tid] = o;
}

// ---------------- MLP GEMM + ELU, double-buffered: C = elu(A @ W^T + b) ----------------
// grid (256, N/64); which: 0 -> ln->a1 (N=512,K=1024), 1 -> a1->a2 (128,512), 2 -> a2->a3 (64,128)
__global__ __launch_bounds__(256) void mlp_gemm(const float* __restrict__ W,
                                                const float* __restrict__ bias, int which) {
    extern __shared__ float sdyn[];
    float* As = sdyn;
    float* Bs = sdyn + 2 * AS_BUF;
    const float* A; float* C; int N, K;
    if (which == 0)      { A = g_ln; C = g_a1; N = 512; K = 1024; }
    else if (which == 1) { A = g_a1; C = g_a2; N = 128; K = 512; }
    else                 { A = g_a2; C = g_a3; N = 64;  K = 128; }

    int tid = threadIdx.x, lane = tid & 31, warp = tid >> 5;
    int m0 = blockIdx.x * 128;
    int n0 = blockIdx.y * 64;
    int wm = warp >> 1, wn = warp & 1;
    int ar = lane >> 2, ac = lane & 3;

    float acc[2][4][4];
#pragma unroll
    for (int i = 0; i < 2; i++)
#pragma unroll
        for (int j = 0; j < 4; j++)
#pragma unroll
            for (int k = 0; k < 4; k++) acc[i][j][k] = 0.f;

    const int NIT = K / 32;
    float4 rA[4], rB[2];

#pragma unroll
    for (int i = 0; i < 4; i++) {
        int q = tid + i * 256;
        int r = q >> 3, k = (q & 7) * 4;
        rA[i] = *(const float4*)(A + (size_t)(m0 + r) * K + k);
    }
#pragma unroll
    for (int i = 0; i < 2; i++) {
        int q = tid + i * 256;
        int r = q >> 3, k = (q & 7) * 4;
        rB[i] = *(const float4*)(W + (size_t)(n0 + r) * K + k);
    }
#pragma unroll
    for (int i = 0; i < 4; i++) {
        int q = tid + i * 256;
        int r = q >> 3, kv = q & 7;
        float* d = &As[r * AS_STRIDE + kv * 4];
        d[0] = tf32f(rA[i].x); d[1] = tf32f(rA[i].y); d[2] = tf32f(rA[i].z); d[3] = tf32f(rA[i].w);
    }
#pragma unroll
    for (int i = 0; i < 2; i++) {
        int q = tid + i * 256;
        int r = q >> 3, kv = q & 7;
        float* d = &Bs[r * AS_STRIDE + kv * 4];
        d[0] = tf32f(rB[i].x); d[1] = tf32f(rB[i].y); d[2] = tf32f(rB[i].z); d[3] = tf32f(rB[i].w);
    }
    __syncthreads();

    for (int it = 0; it < NIT; it++) {
        int buf = it & 1;
        bool more = (it + 1 < NIT);
        int kkn = (it + 1) * 32;

        if (more) {
#pragma unroll
            for (int i = 0; i < 4; i++) {
                int q = tid + i * 256;
                int r = q >> 3, k = kkn + (q & 7) * 4;
                rA[i] = *(const float4*)(A + (size_t)(m0 + r) * K + k);
            }
#pragma unroll
            for (int i = 0; i < 2; i++) {
                int q = tid + i * 256;
                int r = q >> 3, k = kkn + (q & 7) * 4;
                rB[i] = *(const float4*)(W + (size_t)(n0 + r) * K + k);
            }
        }

        const float* Ab = As + buf * AS_BUF;
        const float* Bb = Bs + buf * BS_BUF;
#pragma unroll
        for (int ks = 0; ks < 32; ks += 8) {
            unsigned a[2][4], b[4][2];
#pragma unroll
            for (int mf = 0; mf < 2; mf++) {
                int rb = wm * 32 + mf * 16 + ar;
                a[mf][0] = __float_as_uint(Ab[rb * AS_STRIDE + ks + ac]);
                a[mf][1] = __float_as_uint(Ab[(rb + 8) * AS_STRIDE + ks + ac]);
                a[mf][2] = __float_as_uint(Ab[rb * AS_STRIDE + ks + ac + 4]);
                a[mf][3] = __float_as_uint(Ab[(rb + 8) * AS_STRIDE + ks + ac + 4]);
            }
#pragma unroll
            for (int nf = 0; nf < 4; nf++) {
                int nb = wn * 32 + nf * 8 + ar;
                b[nf][0] = __float_as_uint(Bb[nb * AS_STRIDE + ks + ac]);
                b[nf][1] = __float_as_uint(Bb[nb * AS_STRIDE + ks + ac + 4]);
            }
#pragma unroll
            for (int mf = 0; mf < 2; mf++)
#pragma unroll
                for (int nf = 0; nf < 4; nf++)
                    mma_tf32(acc[mf][nf], a[mf], b[nf]);
        }

        if (more) {
            float* Aw = As + (buf ^ 1) * AS_BUF;
            float* Bw = Bs + (buf ^ 1) * BS_BUF;
#pragma unroll
            for (int i = 0; i < 4; i++) {
                int q = tid + i * 256;
                int r = q >> 3, kv = q & 7;
                float* d = &Aw[r * AS_STRIDE + kv * 4];
                d[0] = tf32f(rA[i].x); d[1] = tf32f(rA[i].y); d[2] = tf32f(rA[i].z); d[3] = tf32f(rA[i].w);
            }
#pragma unroll
            for (int i = 0; i < 2; i++) {
                int q = tid + i * 256;
                int r = q >> 3, kv = q & 7;
                float* d = &Bw[r * AS_STRIDE + kv * 4];
                d[0] = tf32f(rB[i].x); d[1] = tf32f(rB[i].y); d[2] = tf32f(rB[i].z); d[3] = tf32f(rB[i].w);
            }
        }
        __syncthreads();
    }

#pragma unroll
    for (int mf = 0; mf < 2; mf++) {
#pragma unroll
        for (int nf = 0; nf < 4; nf++) {
            int col = n0 + wn * 32 + nf * 8 + ac * 2;
            int r0 = m0 + wm * 32 + mf * 16 + ar;
            float b0 = bias[col], b1 = bias[col + 1];
            C[(size_t)r0 * N + col]           = eluf(acc[mf][nf][0] + b0);
            C[(size_t)r0 * N + col + 1]       = eluf(acc[mf][nf][1] + b1);
            C[(size_t)(r0 + 8) * N + col]     = eluf(acc[mf][nf][2] + b0);
            C[(size_t)(r0 + 8) * N + col + 1] = eluf(acc[mf][nf][3] + b1);
        }
    }
}

// ---------------- final value head: out[r] = dot(a3[r,:64], Wv) + bv ----------------
__global__ __launch_bounds__(256) void value_kernel(const float* __restrict__ Wv,
                                                    const float* __restrict__ bv,
                                                    float* __restrict__ out) {
    int warp = threadIdx.x >> 5, lane = threadIdx.x & 31;
    int row = blockIdx.x * 8 + warp;
    const float* a = g_a3 + (size_t)row * 64;
    float s = a[lane] * Wv[lane] + a[lane + 32] * Wv[lane + 32];
#pragma unroll
    for (int o = 16; o; o >>= 1) s += __shfl_xor_sync(0xffffffffu, s, o);
    if (lane == 0) out[row] = s + bv[0];
}

// ---------------- copy final states into output ----------------
__global__ void copy_states(float* __restrict__ out) {
    const int last = (SEQ - 1) & 1;                 // ping-pong slot of final step
    for (size_t i = blockIdx.x * blockDim.x + threadIdx.x; i < 4 * (size_t)BH;
         i += (size_t)gridDim.x * blockDim.x) {
        float v;
        if (i < BH)                  v = g_h0s[last][i];
        else if (i < 2 * (size_t)BH) v = g_hs[(size_t)(SEQ - 1) * BH + (i - BH)];
        else if (i < 3 * (size_t)BH) v = g_c0s[last][i - 2 * BH];
        else                         v = g_c1s[last][i - 3 * BH];
        out[SEQ * BATCH + i] = v;
    }
}

// ---------------- launch ----------------
extern "C" void kernel_launch(void* const* d_in, const int* in_sizes, int n_in,
                              void* d_out, int out_size) {
    const float* x     = (const float*)d_in[0];
    const int*   done  = (const int*)  d_in[1];
    const float* h0    = (const float*)d_in[2];
    const float* c0    = (const float*)d_in[3];
    const float* Wih0  = (const float*)d_in[4];
    const float* Whh0  = (const float*)d_in[5];
    const float* bih0  = (const float*)d_in[6];
    const float* bhh0  = (const float*)d_in[7];
    const float* Wih1  = (const float*)d_in[8];
    const float* Whh1  = (const float*)d_in[9];
    const float* bih1  = (const float*)d_in[10];
    const float* bhh1  = (const float*)d_in[11];
    const float* ln_g  = (const float*)d_in[12];
    const float* ln_b  = (const float*)d_in[13];
    const float* W1    = (const float*)d_in[14];
    const float* b1    = (const float*)d_in[15];
    const float* W2    = (const float*)d_in[16];
    const float* b2    = (const float*)d_in[17];
    const float* W3    = (const float*)d_in[18];
    const float* b3    = (const float*)d_in[19];
    const float* Wv    = (const float*)d_in[20];
    const float* bv    = (const float*)d_in[21];
    float* out = (float*)d_out;

    cudaFuncSetAttribute(lstm_step_kernel, cudaFuncAttributeMaxDynamicSharedMemorySize, SMEM_BYTES);
    cudaFuncSetAttribute(mlp_gemm,        cudaFuncAttributeMaxDynamicSharedMemorySize, SMEM_BYTES);

    pack_kernel<<<dim3(G4, 2), 256>>>(Wih0, Whh0, bih0, bhh0, Wih1, Whh1, bih1, bhh1);

    for (int t = 0; t < SEQ; t++) {
        lstm_step_kernel<<<dim3(2, 64), 256, SMEM_BYTES>>>(x, done, h0, c0, t, 0);
        lstm_step_kernel<<<dim3(2, 64), 256, SMEM_BYTES>>>(x, done, h0, c0, t, 1);
    }

    ln_kernel<<<SEQ * BATCH, 256>>>(ln_g, ln_b);
    mlp_gemm<<<dim3(256, 8), 256, SMEM_BYTES>>>(W1, b1, 0);
    mlp_gemm<<<dim3(256, 2), 256, SMEM_BYTES>>>(W2, b2, 1);
    mlp_gemm<<<dim3(256, 1), 256, SMEM_BYTES>>>(W3, b3, 2);
    value_kernel<<<SEQ * BATCH / 8, 256>>>(Wv, bv, out);
    copy_states<<<2048, 256>>>(out);
}

// round 6
// speedup vs baseline: 2.4379x; 1.1265x over previous
#include <cuda_runtime.h>
#include <cuda_bf16.h>

#define SEQ   128
#define BATCH 256
#define OBS   64
#define HID   1024
#define G4    4096          // 4*HID
#define K0L0  64            // x part of layer0 K
#define KTOT0 1088          // 64 + 1024
#define KTOT1 2048          // 1024 + 1024
#define NC0   (KTOT0/32)    // 34 chunks
#define NC1   (KTOT1/32)    // 64 chunks
#define BH    (BATCH*HID)

// lstm smem: A double buffer (2 x 128x32, stride 36) + mrow
#define AS_STRIDE 36
#define AS_BUF    (128*AS_STRIDE)                 // 4608 floats
#define LSTM_SMEM_FLOATS (2*AS_BUF + 128)
#define LSTM_SMEM_BYTES  (LSTM_SMEM_FLOATS*4)

// mlp smem: A + B double buffers (old layout)
#define BS_BUF    (64*AS_STRIDE)
#define MLP_SMEM_FLOATS (2*AS_BUF + 2*BS_BUF)
#define MLP_SMEM_BYTES  (MLP_SMEM_FLOATS*4)

// ---------------- scratch (static device memory; no allocations) ----------------
// B weights packed in mma-fragment order:
// idx = ((((nt*2+wn)*NC + chunk)*4 + ksi)*32 + lane)*8 + nf*2 + pair
__device__ float g_PWf0[(size_t)G4 * KTOT0];
__device__ float g_PWf1[(size_t)G4 * KTOT1];
__device__ float g_PB0[G4];
__device__ float g_PB1[G4];
__device__ float g_h0s[2][BH];                // layer0 h state ping-pong
__device__ float g_c0s[2][BH];
__device__ float g_c1s[2][BH];
__device__ float g_hs[(size_t)SEQ * BH];      // layer1 h per step
__device__ float g_ln[(size_t)SEQ * BH];
__device__ float g_a1[(size_t)SEQ * BATCH * 512];
__device__ float g_a2[(size_t)SEQ * BATCH * 128];
__device__ float g_a3[(size_t)SEQ * BATCH * 64];

// ---------------- helpers ----------------
__device__ __forceinline__ unsigned tf32_bits(float x) {
    unsigned u; asm("cvt.rna.tf32.f32 %0, %1;" : "=r"(u) : "f"(x)); return u;
}
__device__ __forceinline__ float tf32f(float x) { return __uint_as_float(tf32_bits(x)); }

__device__ __forceinline__ void mma_tf32(float* c, const unsigned* a, const unsigned* b) {
    asm volatile(
        "mma.sync.aligned.m16n8k8.row.col.f32.tf32.tf32.f32 "
        "{%0,%1,%2,%3}, {%4,%5,%6,%7}, {%8,%9}, {%0,%1,%2,%3};"
        : "+f"(c[0]), "+f"(c[1]), "+f"(c[2]), "+f"(c[3])
        : "r"(a[0]), "r"(a[1]), "r"(a[2]), "r"(a[3]), "r"(b[0]), "r"(b[1]));
}

__device__ __forceinline__ float sigm(float x) { return 1.f / (1.f + __expf(-x)); }
__device__ __forceinline__ float eluf(float x) { return x > 0.f ? x : (__expf(x) - 1.f); }

// ---------------- weight packing into fragment order ----------------
// grid (128, 2): x = nt*2+wn, y = layer; block 256
__global__ void pack_frag(const float* __restrict__ Wih0, const float* __restrict__ Whh0,
                          const float* __restrict__ Wih1, const float* __restrict__ Whh1) {
    int ntwn = blockIdx.x;
    int nt = ntwn >> 1, wn = ntwn & 1;
    int layer = blockIdx.y;
    int lane = threadIdx.x & 31, sub = threadIdx.x >> 5;   // sub = nf*2 + pair
    int nf = sub >> 1, pair = sub & 1;
    int Ktot = layer ? KTOT1 : KTOT0;
    int NC   = layer ? NC1 : NC0;
    int K0   = layer ? HID : K0L0;
    const float* Wih = layer ? Wih1 : Wih0;
    const float* Whh = layer ? Whh1 : Whh0;
    float* dstbase = (layer ? g_PWf1 : g_PWf0) + (size_t)ntwn * ((size_t)NC * 1024);

    int srow = nt * 64 + wn * 32 + nf * 8 + (lane >> 2);   // packed row (unit*4+gate)
    int u = srow >> 2, g = srow & 3;
    int orow = g * HID + u;                                // original weight row

    for (int j = 0; j < NC * 4; j++) {
        int col = (j >> 2) * 32 + (j & 3) * 8 + (lane & 3) + pair * 4;
        float v = (col < K0) ? Wih[(size_t)orow * K0 + col]
                             : Whh[(size_t)orow * HID + (col - K0)];
        dstbase[(size_t)j * 256 + lane * 8 + sub] = tf32f(v);
    }
}

__global__ void pack_bias(const float* __restrict__ bih0, const float* __restrict__ bhh0,
                          const float* __restrict__ bih1, const float* __restrict__ bhh1) {
    int j = blockIdx.x * 256 + threadIdx.x;                // packed row
    int u = j >> 2, g = j & 3;
    int src = g * HID + u;
    if (blockIdx.y == 0) g_PB0[j] = bih0[src] + bhh0[src];
    else                 g_PB1[j] = bih1[src] + bhh1[src];
}

// ---------------- fused LSTM: layer1(t) || layer0(t+1) in one launch ----------------
// mode 0: grid 128, layer0 step t only (prologue)
// mode 1: grid 256, bx<128 -> layer1(t); bx>=128 -> layer0(t+1)
__global__ __launch_bounds__(256, 2) void lstm_comb_kernel(
    const float* __restrict__ x, const int* __restrict__ done,
    const float* __restrict__ in_h0, const float* __restrict__ in_c0,
    int t, int mode)
{
    extern __shared__ float sdyn[];
    float* As   = sdyn;                       // 2 buffers of 128x32 (stride 36)
    float* mrow = sdyn + 2 * AS_BUF;

    int layer, step, bx2;
    if (mode == 0) { layer = 0; step = t; bx2 = blockIdx.x; }
    else if (blockIdx.x < 128) { layer = 1; step = t; bx2 = blockIdx.x; }
    else { layer = 0; step = t + 1; bx2 = blockIdx.x - 128; if (step >= SEQ) return; }

    const float *A0, *Aprev, *cprev, *PWf, *PB;
    float *cout_, *hout;
    int K0len, NC;
    if (layer == 0) {
        A0 = x + (size_t)step * BATCH * OBS; K0len = K0L0; NC = NC0;
        PWf = g_PWf0; PB = g_PB0;
        Aprev = step ? g_h0s[(step - 1) & 1] : in_h0;
        cprev = step ? g_c0s[(step - 1) & 1] : in_c0;
        cout_ = g_c0s[step & 1]; hout = g_h0s[step & 1];
    } else {
        A0 = g_h0s[step & 1]; K0len = HID; NC = NC1;
        PWf = g_PWf1; PB = g_PB1;
        Aprev = step ? (g_hs + (size_t)(step - 1) * BH) : (in_h0 + BH);
        cprev = step ? g_c1s[(step - 1) & 1] : (in_c0 + BH);
        cout_ = g_c1s[step & 1]; hout = g_hs + (size_t)step * BH;
    }
    const int* dt = done + step * BATCH;

    int tid = threadIdx.x, lane = tid & 31, warp = tid >> 5;
    int m0 = (bx2 & 1) * 128;                 // M tile
    int nt = bx2 >> 1;                        // 64-col N tile
    int nrow0 = nt * 64;
    int wm = warp >> 1, wn = warp & 1;        // 4x2 warp grid, 32x32 per warp
    int ar = lane >> 2, ac = lane & 3;

    for (int r = tid; r < 128; r += 256) mrow[r] = 1.f - (float)dt[m0 + r];
    __syncthreads();

    float acc[2][4][4];
#pragma unroll
    for (int i = 0; i < 2; i++)
#pragma unroll
        for (int j = 0; j < 4; j++)
#pragma unroll
            for (int k = 0; k < 4; k++) acc[i][j][k] = 0.f;

    // B fragment stream pointer for this warp-half
    const float* Bthr = PWf + (size_t)(nt * 2 + wn) * ((size_t)NC * 1024) + lane * 8;

    float4 rA[4];
    // ---- prologue: A chunk 0 -> buffer 0 ----
#pragma unroll
    for (int i = 0; i < 4; i++) {
        int q = tid + i * 256;
        int r = q >> 3, k = (q & 7) * 4;
        if (k < K0len) rA[i] = *(const float4*)(A0 + (size_t)(m0 + r) * K0len + k);
        else           rA[i] = *(const float4*)(Aprev + (size_t)(m0 + r) * HID + (k - K0len));
    }
#pragma unroll
    for (int i = 0; i < 4; i++) {
        int q = tid + i * 256;
        int r = q >> 3, kv = q & 7, k = kv * 4;
        float4 v = rA[i];
        if (k >= K0len) { float mm = mrow[r]; v.x *= mm; v.y *= mm; v.z *= mm; v.w *= mm; }
        float* d = &As[r * AS_STRIDE + kv * 4];
        d[0] = tf32f(v.x); d[1] = tf32f(v.y); d[2] = tf32f(v.z); d[3] = tf32f(v.w);
    }
    __syncthreads();

    // B ring: preload j=0
    float4 b0c = *(const float4*)(Bthr);
    float4 b1c = *(const float4*)(Bthr + 4);
    Bthr += 256;

    for (int it = 0; it < NC; it++) {
        int buf = it & 1;
        bool moreA = (it + 1 < NC);
        int kkn = (it + 1) * 32;

        if (moreA) {                          // global prefetch of next A chunk
#pragma unroll
            for (int i = 0; i < 4; i++) {
                int q = tid + i * 256;
                int r = q >> 3, k = kkn + (q & 7) * 4;
                if (k < K0len) rA[i] = *(const float4*)(A0 + (size_t)(m0 + r) * K0len + k);
                else           rA[i] = *(const float4*)(Aprev + (size_t)(m0 + r) * HID + (k - K0len));
            }
        }

        const float* Ab = As + buf * AS_BUF;
#pragma unroll
        for (int ksi = 0; ksi < 4; ksi++) {
            // prefetch next B fragment block (1 ksi ahead)
            float4 b0n, b1n;
            bool moreB = (it * 4 + ksi + 1 < NC * 4);
            if (moreB) {
                b0n = *(const float4*)(Bthr);
                b1n = *(const float4*)(Bthr + 4);
                Bthr += 256;
            }
            int ks = ksi * 8;
            unsigned a[2][4];
#pragma unroll
            for (int mf = 0; mf < 2; mf++) {
                int rb = wm * 32 + mf * 16 + ar;
                a[mf][0] = __float_as_uint(Ab[rb * AS_STRIDE + ks + ac]);
                a[mf][1] = __float_as_uint(Ab[(rb + 8) * AS_STRIDE + ks + ac]);
                a[mf][2] = __float_as_uint(Ab[rb * AS_STRIDE + ks + ac + 4]);
                a[mf][3] = __float_as_uint(Ab[(rb + 8) * AS_STRIDE + ks + ac + 4]);
            }
            unsigned b[4][2];
            b[0][0] = __float_as_uint(b0c.x); b[0][1] = __float_as_uint(b0c.y);
            b[1][0] = __float_as_uint(b0c.z); b[1][1] = __float_as_uint(b0c.w);
            b[2][0] = __float_as_uint(b1c.x); b[2][1] = __float_as_uint(b1c.y);
            b[3][0] = __float_as_uint(b1c.z); b[3][1] = __float_as_uint(b1c.w);
#pragma unroll
            for (int mf = 0; mf < 2; mf++)
#pragma unroll
                for (int nf = 0; nf < 4; nf++)
                    mma_tf32(acc[mf][nf], a[mf], b[nf]);
            b0c = b0n; b1c = b1n;
        }

        if (moreA) {                          // store next A chunk to alt buffer
            float* Aw = As + (buf ^ 1) * AS_BUF;
#pragma unroll
            for (int i = 0; i < 4; i++) {
                int q = tid + i * 256;
                int r = q >> 3, kv = q & 7, k = kkn + kv * 4;
                float4 v = rA[i];
                if (k >= K0len) { float mm = mrow[r]; v.x *= mm; v.y *= mm; v.z *= mm; v.w *= mm; }
                float* d = &Aw[r * AS_STRIDE + kv * 4];
                d[0] = tf32f(v.x); d[1] = tf32f(v.y); d[2] = tf32f(v.z); d[3] = tf32f(v.w);
            }
        }
        __syncthreads();
    }

    // ---- epilogue: bias + gate merge (shfl lane^1) + LSTM cell ----
#pragma unroll
    for (int mf = 0; mf < 2; mf++) {
#pragma unroll
        for (int nf = 0; nf < 4; nf++) {
            int npl = wn * 32 + nf * 8 + ac * 2;
            int nglob = nrow0 + npl;               // packed col = unit*4 + gate
            float bb0 = PB[nglob], bb1 = PB[nglob + 1];
            float v0 = acc[mf][nf][0] + bb0;
            float v1 = acc[mf][nf][1] + bb1;
            float v2 = acc[mf][nf][2] + bb0;
            float v3 = acc[mf][nf][3] + bb1;
            float p0 = __shfl_xor_sync(0xffffffffu, v0, 1);
            float p1 = __shfl_xor_sync(0xffffffffu, v1, 1);
            float p2 = __shfl_xor_sync(0xffffffffu, v2, 1);
            float p3 = __shfl_xor_sync(0xffffffffu, v3, 1);
            if ((lane & 1) == 0) {                 // even lanes hold (i,f); partner (g,o)
                int u = nglob >> 2;
                int r0 = m0 + wm * 32 + mf * 16 + ar;
                {
                    float mm = mrow[r0 - m0];
                    float cp = cprev[(size_t)r0 * HID + u] * mm;
                    float cn = sigm(v1) * cp + sigm(v0) * tanhf(p0);
                    float hn = sigm(p1) * tanhf(cn);
                    cout_[(size_t)r0 * HID + u] = cn;
                    hout[(size_t)r0 * HID + u] = hn;
                }
                {
                    int r1 = r0 + 8;
                    float mm = mrow[r1 - m0];
                    float cp = cprev[(size_t)r1 * HID + u] * mm;
                    float cn = sigm(v3) * cp + sigm(v2) * tanhf(p2);
                    float hn = sigm(p3) * tanhf(cn);
                    cout_[(size_t)r1 * HID + u] = cn;
                    hout[(size_t)r1 * HID + u] = hn;
                }
            }
        }
    }
}

// ---------------- LayerNorm over hidden (32768 rows x 1024) ----------------
__global__ __launch_bounds__(256) void ln_kernel(const float* __restrict__ gam,
                                                 const float* __restrict__ bet) {
    int row = blockIdx.x;
    int tid = threadIdx.x, lane = tid & 31, w = tid >> 5;
    const float4 v = ((const float4*)(g_hs + (size_t)row * HID))[tid];
    float s = v.x + v.y + v.z + v.w;
    float q = v.x * v.x + v.y * v.y + v.z * v.z + v.w * v.w;
    __shared__ float sh[18];
#pragma unroll
    for (int o = 16; o; o >>= 1) {
        s += __shfl_xor_sync(0xffffffffu, s, o);
        q += __shfl_xor_sync(0xffffffffu, q, o);
    }
    if (!lane) { sh[w] = s; sh[w + 8] = q; }
    __syncthreads();
    if (tid == 0) {
        float S = 0.f, Q = 0.f;
        for (int i = 0; i < 8; i++) { S += sh[i]; Q += sh[i + 8]; }
        float mu = S * (1.f / HID);
        float var = Q * (1.f / HID) - mu * mu;
        sh[16] = mu; sh[17] = rsqrtf(var + 1e-5f);
    }
    __syncthreads();
    float mu = sh[16], rs = sh[17];
    float4 g4 = ((const float4*)gam)[tid];
    float4 b4 = ((const float4*)bet)[tid];
    float4 o;
    o.x = (v.x - mu) * rs * g4.x + b4.x;
    o.y = (v.y - mu) * rs * g4.y + b4.y;
    o.z = (v.z - mu) * rs * g4.z + b4.z;
    o.w = (v.w - mu) * rs * g4.w + b4.w;
    ((float4*)(g_ln + (size_t)row * HID))[tid] = o;
}

// ---------------- MLP GEMM + ELU, double-buffered: C = elu(A @ W^T + b) ----------------
__global__ __launch_bounds__(256) void mlp_gemm(const float* __restrict__ W,
                                                const float* __restrict__ bias, int which) {
    extern __shared__ float sdyn[];
    float* As = sdyn;
    float* Bs = sdyn + 2 * AS_BUF;
    const float* A; float* C; int N, K;
    if (which == 0)      { A = g_ln; C = g_a1; N = 512; K = 1024; }
    else if (which == 1) { A = g_a1; C = g_a2; N = 128; K = 512; }
    else                 { A = g_a2; C = g_a3; N = 64;  K = 128; }

    int tid = threadIdx.x, lane = tid & 31, warp = tid >> 5;
    int m0 = blockIdx.x * 128;
    int n0 = blockIdx.y * 64;
    int wm = warp >> 1, wn = warp & 1;
    int ar = lane >> 2, ac = lane & 3;

    float acc[2][4][4];
#pragma unroll
    for (int i = 0; i < 2; i++)
#pragma unroll
        for (int j = 0; j < 4; j++)
#pragma unroll
            for (int k = 0; k < 4; k++) acc[i][j][k] = 0.f;

    const int NIT = K / 32;
    float4 rA[4], rB[2];

#pragma unroll
    for (int i = 0; i < 4; i++) {
        int q = tid + i * 256;
        int r = q >> 3, k = (q & 7) * 4;
        rA[i] = *(const float4*)(A + (size_t)(m0 + r) * K + k);
    }
#pragma unroll
    for (int i = 0; i < 2; i++) {
        int q = tid + i * 256;
        int r = q >> 3, k = (q & 7) * 4;
        rB[i] = *(const float4*)(W + (size_t)(n0 + r) * K + k);
    }
#pragma unroll
    for (int i = 0; i < 4; i++) {
        int q = tid + i * 256;
        int r = q >> 3, kv = q & 7;
        float* d = &As[r * AS_STRIDE + kv * 4];
        d[0] = tf32f(rA[i].x); d[1] = tf32f(rA[i].y); d[2] = tf32f(rA[i].z); d[3] = tf32f(rA[i].w);
    }
#pragma unroll
    for (int i = 0; i < 2; i++) {
        int q = tid + i * 256;
        int r = q >> 3, kv = q & 7;
        float* d = &Bs[r * AS_STRIDE + kv * 4];
        d[0] = tf32f(rB[i].x); d[1] = tf32f(rB[i].y); d[2] = tf32f(rB[i].z); d[3] = tf32f(rB[i].w);
    }
    __syncthreads();

    for (int it = 0; it < NIT; it++) {
        int buf = it & 1;
        bool more = (it + 1 < NIT);
        int kkn = (it + 1) * 32;

        if (more) {
#pragma unroll
            for (int i = 0; i < 4; i++) {
                int q = tid + i * 256;
                int r = q >> 3, k = kkn + (q & 7) * 4;
                rA[i] = *(const float4*)(A + (size_t)(m0 + r) * K + k);
            }
#pragma unroll
            for (int i = 0; i < 2; i++) {
                int q = tid + i * 256;
                int r = q >> 3, k = kkn + (q & 7) * 4;
                rB[i] = *(const float4*)(W + (size_t)(n0 + r) * K + k);
            }
        }

        const float* Ab = As + buf * AS_BUF;
        const float* Bb = Bs + buf * BS_BUF;
#pragma unroll
        for (int ks = 0; ks < 32; ks += 8) {
            unsigned a[2][4], b[4][2];
#pragma unroll
            for (int mf = 0; mf < 2; mf++) {
                int rb = wm * 32 + mf * 16 + ar;
                a[mf][0] = __float_as_uint(Ab[rb * AS_STRIDE + ks + ac]);
                a[mf][1] = __float_as_uint(Ab[(rb + 8) * AS_STRIDE + ks + ac]);
                a[mf][2] = __float_as_uint(Ab[rb * AS_STRIDE + ks + ac + 4]);
                a[mf][3] = __float_as_uint(Ab[(rb + 8) * AS_STRIDE + ks + ac + 4]);
            }
#pragma unroll
            for (int nf = 0; nf < 4; nf++) {
                int nb = wn * 32 + nf * 8 + ar;
                b[nf][0] = __float_as_uint(Bb[nb * AS_STRIDE + ks + ac]);
                b[nf][1] = __float_as_uint(Bb[nb * AS_STRIDE + ks + ac + 4]);
            }
#pragma unroll
            for (int mf = 0; mf < 2; mf++)
#pragma unroll
                for (int nf = 0; nf < 4; nf++)
                    mma_tf32(acc[mf][nf], a[mf], b[nf]);
        }

        if (more) {
            float* Aw = As + (buf ^ 1) * AS_BUF;
            float* Bw = Bs + (buf ^ 1) * BS_BUF;
#pragma unroll
            for (int i = 0; i < 4; i++) {
                int q = tid + i * 256;
                int r = q >> 3, kv = q & 7;
                float* d = &Aw[r * AS_STRIDE + kv * 4];
                d[0] = tf32f(rA[i].x); d[1] = tf32f(rA[i].y); d[2] = tf32f(rA[i].z); d[3] = tf32f(rA[i].w);
            }
#pragma unroll
            for (int i = 0; i < 2; i++) {
                int q = tid + i * 256;
                int r = q >> 3, kv = q & 7;
                float* d = &Bw[r * AS_STRIDE + kv * 4];
                d[0] = tf32f(rB[i].x); d[1] = tf32f(rB[i].y); d[2] = tf32f(rB[i].z); d[3] = tf32f(rB[i].w);
            }
        }
        __syncthreads();
    }

#pragma unroll
    for (int mf = 0; mf < 2; mf++) {
#pragma unroll
        for (int nf = 0; nf < 4; nf++) {
            int col = n0 + wn * 32 + nf * 8 + ac * 2;
            int r0 = m0 + wm * 32 + mf * 16 + ar;
            float b0 = bias[col], b1 = bias[col + 1];
            C[(size_t)r0 * N + col]           = eluf(acc[mf][nf][0] + b0);
            C[(size_t)r0 * N + col + 1]       = eluf(acc[mf][nf][1] + b1);
            C[(size_t)(r0 + 8) * N + col]     = eluf(acc[mf][nf][2] + b0);
            C[(size_t)(r0 + 8) * N + col + 1] = eluf(acc[mf][nf][3] + b1);
        }
    }
}

// ---------------- final value head ----------------
__global__ __launch_bounds__(256) void value_kernel(const float* __restrict__ Wv,
                                                    const float* __restrict__ bv,
                                                    float* __restrict__ out) {
    int warp = threadIdx.x >> 5, lane = threadIdx.x & 31;
    int row = blockIdx.x * 8 + warp;
    const float* a = g_a3 + (size_t)row * 64;
    float s = a[lane] * Wv[lane] + a[lane + 32] * Wv[lane + 32];
#pragma unroll
    for (int o = 16; o; o >>= 1) s += __shfl_xor_sync(0xffffffffu, s, o);
    if (lane == 0) out[row] = s + bv[0];
}

// ---------------- copy final states into output ----------------
__global__ void copy_states(float* __restrict__ out) {
    const int last = (SEQ - 1) & 1;
    for (size_t i = blockIdx.x * blockDim.x + threadIdx.x; i < 4 * (size_t)BH;
         i += (size_t)gridDim.x * blockDim.x) {
        float v;
        if (i < BH)                  v = g_h0s[last][i];
        else if (i < 2 * (size_t)BH) v = g_hs[(size_t)(SEQ - 1) * BH + (i - BH)];
        else if (i < 3 * (size_t)BH) v = g_c0s[last][i - 2 * BH];
        else                         v = g_c1s[last][i - 3 * BH];
        out[SEQ * BATCH + i] = v;
    }
}

// ---------------- launch ----------------
extern "C" void kernel_launch(void* const* d_in, const int* in_sizes, int n_in,
                              void* d_out, int out_size) {
    const float* x     = (const float*)d_in[0];
    const int*   done  = (const int*)  d_in[1];
    const float* h0    = (const float*)d_in[2];
    const float* c0    = (const float*)d_in[3];
    const float* Wih0  = (const float*)d_in[4];
    const float* Whh0  = (const float*)d_in[5];
    const float* bih0  = (const float*)d_in[6];
    const float* bhh0  = (const float*)d_in[7];
    const float* Wih1  = (const float*)d_in[8];
    const float* Whh1  = (const float*)d_in[9];
    const float* bih1  = (const float*)d_in[10];
    const float* bhh1  = (const float*)d_in[11];
    const float* ln_g  = (const float*)d_in[12];
    const float* ln_b  = (const float*)d_in[13];
    const float* W1    = (const float*)d_in[14];
    const float* b1    = (const float*)d_in[15];
    const float* W2    = (const float*)d_in[16];
    const float* b2    = (const float*)d_in[17];
    const float* W3    = (const float*)d_in[18];
    const float* b3    = (const float*)d_in[19];
    const float* Wv    = (const float*)d_in[20];
    const float* bv    = (const float*)d_in[21];
    float* out = (float*)d_out;

    cudaFuncSetAttribute(lstm_comb_kernel, cudaFuncAttributeMaxDynamicSharedMemorySize, LSTM_SMEM_BYTES);
    cudaFuncSetAttribute(mlp_gemm,         cudaFuncAttributeMaxDynamicSharedMemorySize, MLP_SMEM_BYTES);

    pack_frag<<<dim3(128, 2), 256>>>(Wih0, Whh0, Wih1, Whh1);
    pack_bias<<<dim3(16, 2), 256>>>(bih0, bhh0, bih1, bhh1);

    // prologue: layer0 step 0
    lstm_comb_kernel<<<128, 256, LSTM_SMEM_BYTES>>>(x, done, h0, c0, 0, 0);
    // combined: layer1(t) || layer0(t+1)
    for (int t = 0; t < SEQ; t++)
        lstm_comb_kernel<<<256, 256, LSTM_SMEM_BYTES>>>(x, done, h0, c0, t, 1);

    ln_kernel<<<SEQ * BATCH, 256>>>(ln_g, ln_b);
    mlp_gemm<<<dim3(256, 8), 256, MLP_SMEM_BYTES>>>(W1, b1, 0);
    mlp_gemm<<<dim3(256, 2), 256, MLP_SMEM_BYTES>>>(W2, b2, 1);
    mlp_gemm<<<dim3(256, 1), 256, MLP_SMEM_BYTES>>>(W3, b3, 2);
    value_kernel<<<SEQ * BATCH / 8, 256>>>(Wv, bv, out);
    copy_states<<<2048, 256>>>(out);
}

// round 7
// speedup vs baseline: 3.4326x; 1.4080x over previous
#include <cuda_runtime.h>
#include <cuda_bf16.h>

#define SEQ   128
#define BATCH 256
#define OBS   64
#define HID   1024
#define G4    4096          // 4*HID
#define K0L0  64            // x part of layer0 K
#define KTOT0 1088          // 64 + 1024
#define KTOT1 2048          // 1024 + 1024
#define NC0   (KTOT0/32)    // 34 chunks
#define NC1   (KTOT1/32)    // 64 chunks
#define BH    (BATCH*HID)

#define AS_STRIDE 36
#define AS_BUF    (128*AS_STRIDE)     // 4608 floats per stage
#define BS_BUF    (64*AS_STRIDE)      // 2304 floats per stage
#define STAGES 3
#define SMEM_FLOATS (STAGES*(AS_BUF+BS_BUF))
#define SMEM_BYTES  (SMEM_FLOATS*4)   // 82944 B

// ---------------- scratch (static device memory; no allocations) ----------------
__device__ __align__(16) float g_PW0[(size_t)G4 * KTOT0];   // packed tf32 weights, row=unit*4+gate
__device__ __align__(16) float g_PW1[(size_t)G4 * KTOT1];
__device__ __align__(16) float g_PB0[G4];
__device__ __align__(16) float g_PB1[G4];
// raw states (ping-pong by step parity)
__device__ __align__(16) float g_h0r[2][BH];
__device__ __align__(16) float g_c0r[2][BH];
__device__ __align__(16) float g_c1r[2][BH];
__device__ __align__(16) float g_hs[(size_t)SEQ * BH];      // layer1 raw h per step
// pre-masked states: slot s holds value consumed at step s
__device__ __align__(16) float g_h0m[2][BH];
__device__ __align__(16) float g_h1m[2][BH];
__device__ __align__(16) float g_c0m[2][BH];
__device__ __align__(16) float g_c1m[2][BH];
__device__ __align__(16) float g_ln[(size_t)SEQ * BH];
__device__ __align__(16) float g_a1[(size_t)SEQ * BATCH * 512];
__device__ __align__(16) float g_a2[(size_t)SEQ * BATCH * 128];
__device__ __align__(16) float g_a3[(size_t)SEQ * BATCH * 64];

// ---------------- helpers ----------------
__device__ __forceinline__ unsigned tf32_bits(float x) {
    unsigned u; asm("cvt.rna.tf32.f32 %0, %1;" : "=r"(u) : "f"(x)); return u;
}
__device__ __forceinline__ float tf32f(float x) { return __uint_as_float(tf32_bits(x)); }

__device__ __forceinline__ void mma_tf32(float* c, const unsigned* a, const unsigned* b) {
    asm volatile(
        "mma.sync.aligned.m16n8k8.row.col.f32.tf32.tf32.f32 "
        "{%0,%1,%2,%3}, {%4,%5,%6,%7}, {%8,%9}, {%0,%1,%2,%3};"
        : "+f"(c[0]), "+f"(c[1]), "+f"(c[2]), "+f"(c[3])
        : "r"(a[0]), "r"(a[1]), "r"(a[2]), "r"(a[3]), "r"(b[0]), "r"(b[1]));
}

__device__ __forceinline__ void cpasync16(float* smem_ptr, const float* gptr) {
    unsigned s = (unsigned)__cvta_generic_to_shared(smem_ptr);
    asm volatile("cp.async.ca.shared.global [%0], [%1], 16;" :: "r"(s), "l"(gptr));
}
__device__ __forceinline__ void cp_commit() { asm volatile("cp.async.commit_group;"); }
template<int N> __device__ __forceinline__ void cp_wait() {
    asm volatile("cp.async.wait_group %0;" :: "n"(N));
}

__device__ __forceinline__ float sigm(float x) { return 1.f / (1.f + __expf(-x)); }
__device__ __forceinline__ float eluf(float x) { return x > 0.f ? x : (__expf(x) - 1.f); }

// ---------------- weight packing (tf32-rounded, gate-interleaved rows) ----------------
__global__ void pack_kernel(const float* __restrict__ Wih0, const float* __restrict__ Whh0,
                            const float* __restrict__ bih0, const float* __restrict__ bhh0,
                            const float* __restrict__ Wih1, const float* __restrict__ Whh1,
                            const float* __restrict__ bih1, const float* __restrict__ bhh1) {
    int j = blockIdx.x;              // packed row: j = unit*4 + gate
    int u = j >> 2, g = j & 3;
    int src = g * HID + u;
    if (blockIdx.y == 0) {
        for (int k = threadIdx.x; k < KTOT0; k += blockDim.x) {
            float v = (k < K0L0) ? Wih0[src * OBS + k] : Whh0[src * HID + (k - K0L0)];
            g_PW0[(size_t)j * KTOT0 + k] = tf32f(v);
        }
        if (threadIdx.x == 0) g_PB0[j] = bih0[src] + bhh0[src];
    } else {
        for (int k = threadIdx.x; k < KTOT1; k += blockDim.x) {
            float v = (k < HID) ? Wih1[src * HID + k] : Whh1[src * HID + (k - HID)];
            g_PW1[(size_t)j * KTOT1 + k] = tf32f(v);
        }
        if (threadIdx.x == 0) g_PB1[j] = bih1[src] + bhh1[src];
    }
}

// ---------------- initial masked state (step 0) ----------------
__global__ void init_masked(const float* __restrict__ h0, const float* __restrict__ c0,
                            const int* __restrict__ done) {
    size_t i = (size_t)blockIdx.x * blockDim.x + threadIdx.x;   // over BH
    int b = (int)(i / HID);
    float m = 1.f - (float)done[b];
    g_h0m[0][i] = h0[i] * m;
    g_h1m[0][i] = h0[BH + i] * m;
    g_c0m[0][i] = c0[i] * m;
    g_c1m[0][i] = c0[BH + i] * m;
}

// ---------------- fused LSTM: layer1(t) || layer0(t+1), cp.async 3-stage pipeline ----------------
// mode 0: grid 128, layer0 step t only (prologue)
// mode 1: grid 256, bx<128 -> layer1(t); bx>=128 -> layer0(t+1)
__global__ __launch_bounds__(256, 2) void lstm_comb_kernel(
    const float* __restrict__ x, const int* __restrict__ done,
    int t, int mode)
{
    extern __shared__ float sdyn[];
    float* As = sdyn;                         // STAGES x 128x32 (stride 36)
    float* Bs = sdyn + STAGES * AS_BUF;       // STAGES x 64x32

    int layer, step, bx2;
    if (mode == 0) { layer = 0; step = t; bx2 = blockIdx.x; }
    else if (blockIdx.x < 128) { layer = 1; step = t; bx2 = blockIdx.x; }
    else { layer = 0; step = t + 1; bx2 = blockIdx.x - 128; if (step >= SEQ) return; }

    const float *A0, *Aprev, *cprev, *PW, *PB;
    float *hraw, *hm_out, *cm_out, *craw;
    int K0len, NC, Ktot;
    if (layer == 0) {
        A0 = x + (size_t)step * BATCH * OBS; K0len = K0L0; NC = NC0; Ktot = KTOT0;
        PW = g_PW0; PB = g_PB0;
        Aprev = g_h0m[step & 1];
        cprev = g_c0m[step & 1];
        hraw = g_h0r[step & 1]; hm_out = g_h0m[(step + 1) & 1];
        cm_out = g_c0m[(step + 1) & 1]; craw = g_c0r[step & 1];
    } else {
        A0 = g_h0r[step & 1]; K0len = HID; NC = NC1; Ktot = KTOT1;
        PW = g_PW1; PB = g_PB1;
        Aprev = g_h1m[step & 1];
        cprev = g_c1m[step & 1];
        hraw = g_hs + (size_t)step * BH; hm_out = g_h1m[(step + 1) & 1];
        cm_out = g_c1m[(step + 1) & 1]; craw = g_c1r[step & 1];
    }

    int tid = threadIdx.x, lane = tid & 31, warp = tid >> 5;
    int m0 = (bx2 & 1) * 128;                 // M tile
    int nrow0 = (bx2 >> 1) * 64;              // 64-col N tile
    int wm = warp >> 1, wn = warp & 1;        // 4x2 warp grid, 32x32 per warp
    int ar = lane >> 2, ac = lane & 3;

    float acc[2][4][4];
#pragma unroll
    for (int i = 0; i < 2; i++)
#pragma unroll
        for (int j = 0; j < 4; j++)
#pragma unroll
            for (int k = 0; k < 4; k++) acc[i][j][k] = 0.f;

    // issue one chunk's loads into stage st
    auto issue = [&](int ck, int st) {
        int kk = ck * 32;
        bool inx = kk < K0len;                // uniform per chunk (K0len mult of 32)
        const float* base = inx ? A0 + (size_t)m0 * K0len + kk
                                : Aprev + (size_t)m0 * HID + (kk - K0len);
        int rs = inx ? K0len : HID;
        float* Ad = As + st * AS_BUF;
#pragma unroll
        for (int i = 0; i < 4; i++) {
            int q = tid + i * 256; int r = q >> 3; int c4 = (q & 7) * 4;
            cpasync16(&Ad[r * AS_STRIDE + c4], base + (size_t)r * rs + c4);
        }
        const float* bb = PW + (size_t)nrow0 * Ktot + kk;
        float* Bd = Bs + st * BS_BUF;
#pragma unroll
        for (int i = 0; i < 2; i++) {
            int q = tid + i * 256; int r = q >> 3; int c4 = (q & 7) * 4;
            cpasync16(&Bd[r * AS_STRIDE + c4], bb + (size_t)r * Ktot + c4);
        }
        cp_commit();
    };

    issue(0, 0);
    issue(1, 1);

    for (int it = 0; it < NC; it++) {
        if (it < NC - 1) cp_wait<1>(); else cp_wait<0>();
        __syncthreads();
        int nxt = it + 2;
        if (nxt < NC) issue(nxt, nxt % STAGES);

        const float* Ab = As + (it % STAGES) * AS_BUF;
        const float* Bb = Bs + (it % STAGES) * BS_BUF;
#pragma unroll
        for (int ksi = 0; ksi < 4; ksi++) {
            int ks = ksi * 8;
            unsigned a[2][4], b[4][2];
#pragma unroll
            for (int mf = 0; mf < 2; mf++) {
                int rb = wm * 32 + mf * 16 + ar;
                a[mf][0] = tf32_bits(Ab[rb * AS_STRIDE + ks + ac]);
                a[mf][1] = tf32_bits(Ab[(rb + 8) * AS_STRIDE + ks + ac]);
                a[mf][2] = tf32_bits(Ab[rb * AS_STRIDE + ks + ac + 4]);
                a[mf][3] = tf32_bits(Ab[(rb + 8) * AS_STRIDE + ks + ac + 4]);
            }
#pragma unroll
            for (int nf = 0; nf < 4; nf++) {
                int nb = wn * 32 + nf * 8 + ar;
                b[nf][0] = __float_as_uint(Bb[nb * AS_STRIDE + ks + ac]);
                b[nf][1] = __float_as_uint(Bb[nb * AS_STRIDE + ks + ac + 4]);
            }
#pragma unroll
            for (int mf = 0; mf < 2; mf++)
#pragma unroll
                for (int nf = 0; nf < 4; nf++)
                    mma_tf32(acc[mf][nf], a[mf], b[nf]);
        }
        __syncthreads();
    }

    // ---- epilogue: bias + gate merge (shfl lane^1) + LSTM cell + masked stores ----
    const int* dnext = done + (step + 1) * BATCH;
    bool has_next = (step + 1 < SEQ);
#pragma unroll
    for (int mf = 0; mf < 2; mf++) {
#pragma unroll
        for (int nf = 0; nf < 4; nf++) {
            int npl = wn * 32 + nf * 8 + ac * 2;
            int nglob = nrow0 + npl;               // packed col = unit*4 + gate
            float bb0 = PB[nglob], bb1 = PB[nglob + 1];
            float v0 = acc[mf][nf][0] + bb0;
            float v1 = acc[mf][nf][1] + bb1;
            float v2 = acc[mf][nf][2] + bb0;
            float v3 = acc[mf][nf][3] + bb1;
            float p0 = __shfl_xor_sync(0xffffffffu, v0, 1);
            float p1 = __shfl_xor_sync(0xffffffffu, v1, 1);
            float p2 = __shfl_xor_sync(0xffffffffu, v2, 1);
            float p3 = __shfl_xor_sync(0xffffffffu, v3, 1);
            if ((lane & 1) == 0) {                 // even lanes hold (i,f); partner (g,o)
                int u = nglob >> 2;
                int r0 = m0 + wm * 32 + mf * 16 + ar;
                {
                    float mn = has_next ? 1.f - (float)dnext[r0] : 0.f;
                    float cp = cprev[(size_t)r0 * HID + u];        // pre-masked
                    float cn = sigm(v1) * cp + sigm(v0) * tanhf(p0);
                    float hn = sigm(p1) * tanhf(cn);
                    size_t o = (size_t)r0 * HID + u;
                    hraw[o] = hn; hm_out[o] = hn * mn;
                    cm_out[o] = cn * mn; craw[o] = cn;
                }
                {
                    int r1 = r0 + 8;
                    float mn = has_next ? 1.f - (float)dnext[r1] : 0.f;
                    float cp = cprev[(size_t)r1 * HID + u];
                    float cn = sigm(v3) * cp + sigm(v2) * tanhf(p2);
                    float hn = sigm(p3) * tanhf(cn);
                    size_t o = (size_t)r1 * HID + u;
                    hraw[o] = hn; hm_out[o] = hn * mn;
                    cm_out[o] = cn * mn; craw[o] = cn;
                }
            }
        }
    }
}

// ---------------- LayerNorm over hidden (32768 rows x 1024) ----------------
__global__ __launch_bounds__(256) void ln_kernel(const float* __restrict__ gam,
                                                 const float* __restrict__ bet) {
    int row = blockIdx.x;
    int tid = threadIdx.x, lane = tid & 31, w = tid >> 5;
    const float4 v = ((const float4*)(g_hs + (size_t)row * HID))[tid];
    float s = v.x + v.y + v.z + v.w;
    float q = v.x * v.x + v.y * v.y + v.z * v.z + v.w * v.w;
    __shared__ float sh[18];
#pragma unroll
    for (int o = 16; o; o >>= 1) {
        s += __shfl_xor_sync(0xffffffffu, s, o);
        q += __shfl_xor_sync(0xffffffffu, q, o);
    }
    if (!lane) { sh[w] = s; sh[w + 8] = q; }
    __syncthreads();
    if (tid == 0) {
        float S = 0.f, Q = 0.f;
        for (int i = 0; i < 8; i++) { S += sh[i]; Q += sh[i + 8]; }
        float mu = S * (1.f / HID);
        float var = Q * (1.f / HID) - mu * mu;
        sh[16] = mu; sh[17] = rsqrtf(var + 1e-5f);
    }
    __syncthreads();
    float mu = sh[16], rs = sh[17];
    float4 g4 = ((const float4*)gam)[tid];
    float4 b4 = ((const float4*)bet)[tid];
    float4 o;
    o.x = (v.x - mu) * rs * g4.x + b4.x;
    o.y = (v.y - mu) * rs * g4.y + b4.y;
    o.z = (v.z - mu) * rs * g4.z + b4.z;
    o.w = (v.w - mu) * rs * g4.w + b4.w;
    ((float4*)(g_ln + (size_t)row * HID))[tid] = o;
}

// ---------------- MLP GEMM + ELU, cp.async 3-stage: C = elu(A @ W^T + b) ----------------
__global__ __launch_bounds__(256, 2) void mlp_gemm(const float* __restrict__ W,
                                                   const float* __restrict__ bias, int which) {
    extern __shared__ float sdyn[];
    float* As = sdyn;
    float* Bs = sdyn + STAGES * AS_BUF;
    const float* A; float* C; int N, K;
    if (which == 0)      { A = g_ln; C = g_a1; N = 512; K = 1024; }
    else if (which == 1) { A = g_a1; C = g_a2; N = 128; K = 512; }
    else                 { A = g_a2; C = g_a3; N = 64;  K = 128; }

    int tid = threadIdx.x, lane = tid & 31, warp = tid >> 5;
    int m0 = blockIdx.x * 128;
    int n0 = blockIdx.y * 64;
    int wm = warp >> 1, wn = warp & 1;
    int ar = lane >> 2, ac = lane & 3;

    float acc[2][4][4];
#pragma unroll
    for (int i = 0; i < 2; i++)
#pragma unroll
        for (int j = 0; j < 4; j++)
#pragma unroll
            for (int k = 0; k < 4; k++) acc[i][j][k] = 0.f;

    const int NC = K / 32;

    auto issue = [&](int ck, int st) {
        int kk = ck * 32;
        const float* ab = A + (size_t)m0 * K + kk;
        float* Ad = As + st * AS_BUF;
#pragma unroll
        for (int i = 0; i < 4; i++) {
            int q = tid + i * 256; int r = q >> 3; int c4 = (q & 7) * 4;
            cpasync16(&Ad[r * AS_STRIDE + c4], ab + (size_t)r * K + c4);
        }
        const float* bb = W + (size_t)n0 * K + kk;
        float* Bd = Bs + st * BS_BUF;
#pragma unroll
        for (int i = 0; i < 2; i++) {
            int q = tid + i * 256; int r = q >> 3; int c4 = (q & 7) * 4;
            cpasync16(&Bd[r * AS_STRIDE + c4], bb + (size_t)r * K + c4);
        }
        cp_commit();
    };

    issue(0, 0);
    issue(1, 1);

    for (int it = 0; it < NC; it++) {
        if (it < NC - 1) cp_wait<1>(); else cp_wait<0>();
        __syncthreads();
        int nxt = it + 2;
        if (nxt < NC) issue(nxt, nxt % STAGES);

        const float* Ab = As + (it % STAGES) * AS_BUF;
        const float* Bb = Bs + (it % STAGES) * BS_BUF;
#pragma unroll
        for (int ksi = 0; ksi < 4; ksi++) {
            int ks = ksi * 8;
            unsigned a[2][4], b[4][2];
#pragma unroll
            for (int mf = 0; mf < 2; mf++) {
                int rb = wm * 32 + mf * 16 + ar;
                a[mf][0] = tf32_bits(Ab[rb * AS_STRIDE + ks + ac]);
                a[mf][1] = tf32_bits(Ab[(rb + 8) * AS_STRIDE + ks + ac]);
                a[mf][2] = tf32_bits(Ab[rb * AS_STRIDE + ks + ac + 4]);
                a[mf][3] = tf32_bits(Ab[(rb + 8) * AS_STRIDE + ks + ac + 4]);
            }
#pragma unroll
            for (int nf = 0; nf < 4; nf++) {
                int nb = wn * 32 + nf * 8 + ar;
                b[nf][0] = tf32_bits(Bb[nb * AS_STRIDE + ks + ac]);
                b[nf][1] = tf32_bits(Bb[nb * AS_STRIDE + ks + ac + 4]);
            }
#pragma unroll
            for (int mf = 0; mf < 2; mf++)
#pragma unroll
                for (int nf = 0; nf < 4; nf++)
                    mma_tf32(acc[mf][nf], a[mf], b[nf]);
        }
        __syncthreads();
    }

#pragma unroll
    for (int mf = 0; mf < 2; mf++) {
#pragma unroll
        for (int nf = 0; nf < 4; nf++) {
            int col = n0 + wn * 32 + nf * 8 + ac * 2;
            int r0 = m0 + wm * 32 + mf * 16 + ar;
            float b0 = bias[col], b1 = bias[col + 1];
            C[(size_t)r0 * N + col]           = eluf(acc[mf][nf][0] + b0);
            C[(size_t)r0 * N + col + 1]       = eluf(acc[mf][nf][1] + b1);
            C[(size_t)(r0 + 8) * N + col]     = eluf(acc[mf][nf][2] + b0);
            C[(size_t)(r0 + 8) * N + col + 1] = eluf(acc[mf][nf][3] + b1);
        }
    }
}

// ---------------- final value head ----------------
__global__ __launch_bounds__(256) void value_kernel(const float* __restrict__ Wv,
                                                    const float* __restrict__ bv,
                                                    float* __restrict__ out) {
    int warp = threadIdx.x >> 5, lane = threadIdx.x & 31;
    int row = blockIdx.x * 8 + warp;
    const float* a = g_a3 + (size_t)row * 64;
    float s = a[lane] * Wv[lane] + a[lane + 32] * Wv[lane + 32];
#pragma unroll
    for (int o = 16; o; o >>= 1) s += __shfl_xor_sync(0xffffffffu, s, o);
    if (lane == 0) out[row] = s + bv[0];
}

// ---------------- copy final states into output ----------------
__global__ void copy_states(float* __restrict__ out) {
    const int last = (SEQ - 1) & 1;                 // = 1
    for (size_t i = blockIdx.x * blockDim.x + threadIdx.x; i < 4 * (size_t)BH;
         i += (size_t)gridDim.x * blockDim.x) {
        float v;
        if (i < BH)                  v = g_h0r[last][i];
        else if (i < 2 * (size_t)BH) v = g_hs[(size_t)(SEQ - 1) * BH + (i - BH)];
        else if (i < 3 * (size_t)BH) v = g_c0r[last][i - 2 * BH];
        else                         v = g_c1r[last][i - 3 * BH];
        out[SEQ * BATCH + i] = v;
    }
}

// ---------------- launch ----------------
extern "C" void kernel_launch(void* const* d_in, const int* in_sizes, int n_in,
                              void* d_out, int out_size) {
    const float* x     = (const float*)d_in[0];
    const int*   done  = (const int*)  d_in[1];
    const float* h0    = (const float*)d_in[2];
    const float* c0    = (const float*)d_in[3];
    const float* Wih0  = (const float*)d_in[4];
    const float* Whh0  = (const float*)d_in[5];
    const float* bih0  = (const float*)d_in[6];
    const float* bhh0  = (const float*)d_in[7];
    const float* Wih1  = (const float*)d_in[8];
    const float* Whh1  = (const float*)d_in[9];
    const float* bih1  = (const float*)d_in[10];
    const float* bhh1  = (const float*)d_in[11];
    const float* ln_g  = (const float*)d_in[12];
    const float* ln_b  = (const float*)d_in[13];
    const float* W1    = (const float*)d_in[14];
    const float* b1    = (const float*)d_in[15];
    const float* W2    = (const float*)d_in[16];
    const float* b2    = (const float*)d_in[17];
    const float* W3    = (const float*)d_in[18];
    const float* b3    = (const float*)d_in[19];
    const float* Wv    = (const float*)d_in[20];
    const float* bv    = (const float*)d_in[21];
    float* out = (float*)d_out;

    cudaFuncSetAttribute(lstm_comb_kernel, cudaFuncAttributeMaxDynamicSharedMemorySize, SMEM_BYTES);
    cudaFuncSetAttribute(mlp_gemm,         cudaFuncAttributeMaxDynamicSharedMemorySize, SMEM_BYTES);

    pack_kernel<<<dim3(G4, 2), 256>>>(Wih0, Whh0, bih0, bhh0, Wih1, Whh1, bih1, bhh1);
    init_masked<<<BH / 256, 256>>>(h0, c0, done);

    // prologue: layer0 step 0
    lstm_comb_kernel<<<128, 256, SMEM_BYTES>>>(x, done, 0, 0);
    // combined: layer1(t) || layer0(t+1)
    for (int t = 0; t < SEQ; t++)
        lstm_comb_kernel<<<256, 256, SMEM_BYTES>>>(x, done, t, 1);

    ln_kernel<<<SEQ * BATCH, 256>>>(ln_g, ln_b);
    mlp_gemm<<<dim3(256, 8), 256, SMEM_BYTES>>>(W1, b1, 0);
    mlp_gemm<<<dim3(256, 2), 256, SMEM_BYTES>>>(W2, b2, 1);
    mlp_gemm<<<dim3(256, 1), 256, SMEM_BYTES>>>(W3, b3, 2);
    value_kernel<<<SEQ * BATCH / 8, 256>>>(Wv, bv, out);
    copy_states<<<2048, 256>>>(out);
}